// round 1
// baseline (speedup 1.0000x reference)
#include <cuda_runtime.h>

// DynamicConvolution: B=16, C_in=C_out=128, K=3, H=W=64, pad=1, fp32.
// Round 1: FMA-bound SIMT implicit GEMM (tap-shift form), weight repack
// pre-pass into a __device__ scratch so A-tiles load coalesced.

#define BB 16
#define CI 128
#define CO 128
#define HW 4096   // 64*64

// Repacked weights: Wt[b][rs][cin][cout]  (9.4 MB static scratch — allowed)
__device__ float g_wt[BB * 9 * CI * CO];

__global__ __launch_bounds__(256) void repack_kernel(const float* __restrict__ w) {
    int idx = blockIdx.x * 256 + threadIdx.x;     // over BB*9*CI*CO = 2,359,296
    int cout = idx & 127;
    int cin  = (idx >> 7) & 127;
    int t14  = idx >> 14;                          // = b*9 + rs
    int rs   = t14 % 9;
    int b    = t14 / 9;
    // src: W[b][cout][cin][r][s], rs = r*3+s
    g_wt[idx] = w[(((b * CO + cout) * CI + cin) * 9) + rs];
}

__global__ __launch_bounds__(256, 2)
void conv_kernel(const float* __restrict__ x, float* __restrict__ out) {
    __shared__ float As[16][128];   // [k][cout]
    __shared__ float Bs[16][132];   // [k][n], padded row (528B, 16B-aligned)

    const int b   = blockIdx.y;       // sample
    const int nt  = blockIdx.x;       // spatial tile: 128 outputs = 2 image rows
    const int h0  = nt << 1;
    const int tid = threadIdx.x;
    const int tx  = tid & 15;         // n-group   (tx*8 .. tx*8+7)
    const int ty  = tid >> 4;         // cout-group (ty*8 .. ty*8+7)

    float acc[8][8];
#pragma unroll
    for (int i = 0; i < 8; i++)
#pragma unroll
        for (int j = 0; j < 8; j++) acc[i][j] = 0.f;

    const float* xb = x + (size_t)b * CI * HW;
    const float* wb = g_wt + (size_t)b * 9 * CI * CO;

    for (int rs = 0; rs < 9; ++rs) {
        const int r = rs / 3 - 1;            // row shift -1..1
        const int s = rs % 3 - 1;            // col shift -1..1
        const float* wrs = wb + rs * CI * CO;

        for (int c0 = 0; c0 < CI; c0 += 16) {
            __syncthreads();
            // --- load A tile: 16 x 128, coalesced float4 (repacked layout) ---
#pragma unroll
            for (int t = 0; t < 2; ++t) {
                int fi = tid + t * 256;       // 512 float4s
                int k  = fi >> 5;
                int m4 = (fi & 31) << 2;
                *(float4*)(&As[k][m4]) = *(const float4*)(wrs + (c0 + k) * CO + m4);
            }
            // --- load B tile: 16 x 128, shifted + boundary-masked input ---
#pragma unroll
            for (int t = 0; t < 8; ++t) {
                int e  = tid + t * 256;       // 2048 elements
                int k  = e >> 7;
                int n  = e & 127;
                int hs = h0 + (n >> 6) + r;
                int ws = (n & 63) + s;
                float v = 0.f;
                if ((unsigned)hs < 64u && (unsigned)ws < 64u)
                    v = __ldg(xb + (c0 + k) * HW + (hs << 6) + ws);
                Bs[k][n] = v;
            }
            __syncthreads();
            // --- 8x8 register-tile FMA over 16 k-steps ---
#pragma unroll
            for (int k = 0; k < 16; ++k) {
                float a[8], bv[8];
                *(float4*)(a)      = *(float4*)(&As[k][ty * 8]);
                *(float4*)(a + 4)  = *(float4*)(&As[k][ty * 8 + 4]);
                *(float4*)(bv)     = *(float4*)(&Bs[k][tx * 8]);
                *(float4*)(bv + 4) = *(float4*)(&Bs[k][tx * 8 + 4]);
#pragma unroll
                for (int i = 0; i < 8; i++)
#pragma unroll
                    for (int j = 0; j < 8; j++)
                        acc[i][j] = fmaf(a[i], bv[j], acc[i][j]);
            }
        }
    }

    // --- write 8x8 per thread, two float4 stores per row ---
#pragma unroll
    for (int i = 0; i < 8; i++) {
        float* o = out + ((size_t)b * CO + ty * 8 + i) * HW + nt * 128 + tx * 8;
        *(float4*)o       = make_float4(acc[i][0], acc[i][1], acc[i][2], acc[i][3]);
        *(float4*)(o + 4) = make_float4(acc[i][4], acc[i][5], acc[i][6], acc[i][7]);
    }
}

extern "C" void kernel_launch(void* const* d_in, const int* in_sizes, int n_in,
                              void* d_out, int out_size) {
    const float* feat = (const float*)d_in[0];   // (16,128,64,64)
    const float* wker = (const float*)d_in[1];   // (16,128,128,3,3)
    float* out = (float*)d_out;                  // (16,128,64,64)

    repack_kernel<<<(BB * 9 * CI * CO) / 256, 256>>>(wker);
    dim3 grid(32, BB);                           // 32 spatial tiles x 16 samples
    conv_kernel<<<grid, 256>>>(feat, out);
}

// round 3
// speedup vs baseline: 2.8450x; 2.8450x over previous
#include <cuda_runtime.h>
#include <cstdint>

// DynamicConvolution: B=16, Cin=Cout=128, K=3, H=W=64, pad=1, fp32.
// R3: tf32 mma.sync implicit GEMM (tcgen05 is rejected by the harness's plain
// sm_103 PTX target). Per sample: C[128,4096] = W[128,1152] x im2col, tap-shift.
// CTA = 128 cout x 256 spatial, 8 warps x (64x64), double-buffered smem.

#define BB 16
#define CI 128
#define CO 128
#define HW 4096

__device__ float g_xr[(size_t)BB * HW * CI];      // 32 MB NHWC tf32-rounded input
__device__ float g_wt[(size_t)BB * 9 * CI * CO];  // 9.4 MB weights [b][rs][cin][cout], tf32

__device__ __forceinline__ float tf32r(float x) {
    uint32_t u; asm("cvt.rna.tf32.f32 %0, %1;" : "=r"(u) : "f"(x));
    return __uint_as_float(u);
}

// ---- pre-pass: weights [b][cout][cin][rs] -> [b][rs][cin][cout], tf32 ----
__global__ __launch_bounds__(256) void prep_w(const float* __restrict__ w) {
    __shared__ float tw[8 * 1152];
    int cg = blockIdx.x, b = blockIdx.y;           // cout group of 8
    const float* src = w + ((size_t)(b * CO + cg * 8)) * 1152;
    for (int i = threadIdx.x; i < 8 * 1152; i += 256) tw[i] = src[i];
    __syncthreads();
    float* dst = g_wt + (size_t)b * 9 * CI * CO;
    for (int j = threadIdx.x; j < 8 * 1152; j += 256) {
        int co = j & 7, cin = (j >> 3) & 127, rs = j >> 10;   // j = rs*1024 + cin*8 + co
        dst[(rs * CI + cin) * CO + cg * 8 + co] = tf32r(tw[co * 1152 + cin * 9 + rs]);
    }
}

// ---- pre-pass: input NCHW -> NHWC, tf32 ----
__global__ __launch_bounds__(256) void prep_x(const float* __restrict__ x) {
    __shared__ float t[64][129];
    int b = blockIdx.x >> 6, h = blockIdx.x & 63;
    const float* src = x + (size_t)b * CI * HW + h * 64;
    for (int c0 = 0; c0 < CI; c0 += 4) {
        int c = c0 + (threadIdx.x >> 6), w = threadIdx.x & 63;
        t[w][c] = src[(size_t)c * HW + w];
    }
    __syncthreads();
    float* dst = g_xr + ((size_t)b * 64 + h) * 64 * CI;
    for (int w0 = 0; w0 < 64; w0 += 2) {
        int w = w0 + (threadIdx.x >> 7), c = threadIdx.x & 127;
        dst[(size_t)w * CI + c] = tf32r(t[w][c]);
    }
}

// ---- main conv ----
// smem (floats): A0 @0 (16x136), A1 @2176, B0 @4352 (256x20), B1 @9472. 58368 B.
__global__ __launch_bounds__(256, 1) void conv_kernel(float* __restrict__ out) {
    extern __shared__ float sm[];
    const int tid = threadIdx.x, wid = tid >> 5, lane = tid & 31;
    const int b = blockIdx.y, nt = blockIdx.x;
    const int h4 = nt << 2;                 // 4 image rows per CTA
    const int m_base = (wid & 1) << 6;      // warp grid: 2 (m) x 4 (n)
    const int n_base = (wid >> 1) << 6;
    const int qid = lane >> 2, tig = lane & 3;

    const float* xb = g_xr + (size_t)b * HW * CI;
    const float* wb = g_wt + (size_t)b * 9 * CI * CO;

    float acc[4][8][4];
#pragma unroll
    for (int f = 0; f < 4; f++)
#pragma unroll
        for (int j = 0; j < 8; j++)
#pragma unroll
            for (int c = 0; c < 4; c++) acc[f][j][c] = 0.f;

    float4 aR[2], bR[4];

    auto LDG = [&](int it) {
        int rs = it >> 3, cc = (it & 7) << 4;      // tap, cin chunk base
        int rdiv = rs / 3;
        int r = rdiv - 1, s = rs - rdiv * 3 - 1;
        const float* wrs = wb + (rs * CI + cc) * CO;
#pragma unroll
        for (int t = 0; t < 2; t++) {              // A: 16k x 128m
            int idx = tid + (t << 8);
            int k = idx >> 5, m4 = (idx & 31) << 2;
            aR[t] = *(const float4*)(wrs + k * CO + m4);
        }
#pragma unroll
        for (int t = 0; t < 4; t++) {              // B: 256n x 16k (NHWC, shifted)
            int idx = tid + (t << 8);
            int n = idx >> 2, ks4 = (idx & 3) << 2;
            int h = h4 + (n >> 6) + r, w = (n & 63) + s;
            float4 v = make_float4(0.f, 0.f, 0.f, 0.f);
            if ((unsigned)h < 64u && (unsigned)w < 64u)
                v = *(const float4*)(xb + (size_t)((h << 6) + w) * CI + cc + ks4);
            bR[t] = v;
        }
    };
    auto STS = [&](int st) {
        float* As = sm + st * 2176;
        float* Bs = sm + 4352 + st * 5120;
#pragma unroll
        for (int t = 0; t < 2; t++) {
            int idx = tid + (t << 8);
            int k = idx >> 5, m4 = (idx & 31) << 2;
            *(float4*)(As + k * 136 + m4) = aR[t];
        }
#pragma unroll
        for (int t = 0; t < 4; t++) {
            int idx = tid + (t << 8);
            int n = idx >> 2, ks4 = (idx & 3) << 2;
            *(float4*)(Bs + n * 20 + ks4) = bR[t];
        }
    };

    LDG(0); STS(0); __syncthreads();

    for (int it = 0; it < 72; ++it) {
        int st = it & 1;
        if (it < 71) LDG(it + 1);
        const float* As = sm + st * 2176;
        const float* Bs = sm + 4352 + st * 5120;
#pragma unroll
        for (int ks = 0; ks < 2; ++ks) {
            const int k0 = ks << 3;
            uint32_t a[4][4], bq[8][2];
            const float* Ak = As + (k0 + tig) * 136 + m_base + qid;
#pragma unroll
            for (int f = 0; f < 4; ++f) {
                a[f][0] = __float_as_uint(Ak[16 * f]);
                a[f][1] = __float_as_uint(Ak[16 * f + 8]);
                a[f][2] = __float_as_uint(Ak[16 * f + 4 * 136]);
                a[f][3] = __float_as_uint(Ak[16 * f + 8 + 4 * 136]);
            }
            const float* Bk = Bs + (n_base + qid) * 20 + k0 + tig;
#pragma unroll
            for (int j = 0; j < 8; ++j) {
                bq[j][0] = __float_as_uint(Bk[j * 160]);
                bq[j][1] = __float_as_uint(Bk[j * 160 + 4]);
            }
#pragma unroll
            for (int f = 0; f < 4; ++f)
#pragma unroll
                for (int j = 0; j < 8; ++j)
                    asm volatile(
                        "mma.sync.aligned.m16n8k8.row.col.f32.tf32.tf32.f32 "
                        "{%0,%1,%2,%3}, {%4,%5,%6,%7}, {%8,%9}, {%0,%1,%2,%3};"
                        : "+f"(acc[f][j][0]), "+f"(acc[f][j][1]),
                          "+f"(acc[f][j][2]), "+f"(acc[f][j][3])
                        : "r"(a[f][0]), "r"(a[f][1]), "r"(a[f][2]), "r"(a[f][3]),
                          "r"(bq[j][0]), "r"(bq[j][1]));
        }
        if (it < 71) STS(st ^ 1);
        __syncthreads();
    }

    // epilogue: c0,c1 -> (row, 2 cols), c2,c3 -> (row+8, 2 cols)
#pragma unroll
    for (int f = 0; f < 4; ++f) {
        int co = m_base + 16 * f + qid;
        float* o0 = out + ((size_t)(b * CO + co)) * HW + (nt << 8) + n_base + 2 * tig;
        float* o1 = o0 + 8 * HW;
#pragma unroll
        for (int j = 0; j < 8; ++j) {
            *(float2*)(o0 + 8 * j) = make_float2(acc[f][j][0], acc[f][j][1]);
            *(float2*)(o1 + 8 * j) = make_float2(acc[f][j][2], acc[f][j][3]);
        }
    }
}

extern "C" void kernel_launch(void* const* d_in, const int* in_sizes, int n_in,
                              void* d_out, int out_size) {
    const float* feat = (const float*)d_in[0];   // (16,128,64,64)
    const float* wker = (const float*)d_in[1];   // (16,128,128,3,3)
    float* out = (float*)d_out;

    cudaFuncSetAttribute(conv_kernel, cudaFuncAttributeMaxDynamicSharedMemorySize, 58368);

    prep_w<<<dim3(16, BB), 256>>>(wker);         // 16 cout-groups x 16 samples
    prep_x<<<BB * 64, 256>>>(feat);
    conv_kernel<<<dim3(16, BB), 256, 58368>>>(out);
}

// round 4
// speedup vs baseline: 3.0644x; 1.0771x over previous
#include <cuda_runtime.h>
#include <cstdint>

// DynamicConvolution: B=16, Cin=Cout=128, K=3, H=W=64, pad=1, fp32.
// R4: tf32 mma.sync implicit GEMM with cp.async 3-stage pipeline + ldmatrix
// fragment loads. CTA = 128 cout x 256 spatial, 8 warps x (64x64).

#define BB 16
#define CI 128
#define CO 128
#define HW 4096

__device__ float g_xr[(size_t)BB * HW * CI];      // NHWC tf32-rounded input
__device__ float g_wt[(size_t)BB * 9 * CO * CI];  // [b][rs][cout][cin], tf32

__device__ __forceinline__ float tf32r(float x) {
    uint32_t u; asm("cvt.rna.tf32.f32 %0, %1;" : "=r"(u) : "f"(x));
    return __uint_as_float(u);
}
__device__ __forceinline__ uint32_t smem_u32(const void* p) {
    uint32_t a; asm("{ .reg .u64 t; cvta.to.shared.u64 t, %1; cvt.u32.u64 %0, t; }" : "=r"(a) : "l"(p));
    return a;
}
__device__ __forceinline__ void ldm_x4(uint32_t* r, uint32_t addr) {
    asm volatile("ldmatrix.sync.aligned.m8n8.x4.shared.b16 {%0,%1,%2,%3}, [%4];"
                 : "=r"(r[0]), "=r"(r[1]), "=r"(r[2]), "=r"(r[3]) : "r"(addr));
}

// ---- pre-pass: weights [b][cout][cin][rs] -> [b][rs][cout][cin], tf32 ----
__global__ __launch_bounds__(256) void prep_w(const float* __restrict__ w) {
    __shared__ float tw[8 * 1152];
    int cg = blockIdx.x, b = blockIdx.y;                 // cout group of 8
    const float* src = w + ((size_t)(b * CO + cg * 8)) * 1152;
    for (int i = threadIdx.x; i < 8 * 1152; i += 256) tw[i] = src[i];
    __syncthreads();
    for (int j = threadIdx.x; j < 8 * 1152; j += 256) {
        int rs = j >> 10, co8 = (j >> 7) & 7, cin = j & 127;
        g_wt[(((size_t)(b * 9 + rs)) * CO + cg * 8 + co8) * CI + cin] =
            tf32r(tw[co8 * 1152 + cin * 9 + rs]);
    }
}

// ---- pre-pass: input NCHW -> NHWC, tf32 ----
__global__ __launch_bounds__(256) void prep_x(const float* __restrict__ x) {
    __shared__ float t[64][129];
    int b = blockIdx.x >> 6, h = blockIdx.x & 63;
    const float* src = x + (size_t)b * CI * HW + h * 64;
    for (int c0 = 0; c0 < CI; c0 += 4) {
        int c = c0 + (threadIdx.x >> 6), w = threadIdx.x & 63;
        t[w][c] = src[(size_t)c * HW + w];
    }
    __syncthreads();
    float* dst = g_xr + ((size_t)b * 64 + h) * 64 * CI;
    for (int w0 = 0; w0 < 64; w0 += 2) {
        int w = w0 + (threadIdx.x >> 7), c = threadIdx.x & 127;
        dst[(size_t)w * CI + c] = tf32r(t[w][c]);
    }
}

// ---- main conv ----
static constexpr int AROW = 36;                       // 32 floats + 4 pad
static constexpr int A_FLOATS = 128 * AROW;           // 4608
static constexpr int B_FLOATS = 256 * AROW;           // 9216
static constexpr int STG = A_FLOATS + B_FLOATS;       // 13824 floats / stage
static constexpr int SMEM_BYTES = 3 * STG * 4;        // 165888

__global__ __launch_bounds__(256, 1) void conv_kernel(float* __restrict__ out) {
    extern __shared__ float sm[];
    const uint32_t sb = smem_u32(sm);
    const int tid = threadIdx.x, wid = tid >> 5, lane = tid & 31;
    const int b = blockIdx.y, nt = blockIdx.x;
    const int h4 = nt << 2;                           // 4 image rows / CTA
    const int mb = (wid & 1) << 6, nb = (wid >> 1) << 6;
    const int qid = lane >> 2, tig = lane & 3;

    // ldmatrix row/k-half selects
    const int arow = ((lane >> 3) & 1) * 8 + (lane & 7);
    const int akh  = (lane >> 4) & 1;
    const int brow = ((lane >> 4) & 1) * 8 + (lane & 7);
    const int bkh  = (lane >> 3) & 1;

    const float* xb = g_xr + (size_t)b * HW * CI;
    const float* wb = g_wt + (size_t)b * 9 * CO * CI;

    float acc[4][8][4];
#pragma unroll
    for (int f = 0; f < 4; f++)
#pragma unroll
        for (int j = 0; j < 8; j++)
#pragma unroll
            for (int c = 0; c < 4; c++) acc[f][j][c] = 0.f;

    auto issue = [&](int it) {
        const int st = it % 3, rs = it >> 2, c0 = (it & 3) << 5;
        const int rd = rs / 3, r = rd - 1, s = rs - rd * 3 - 1;
        const uint32_t abase = sb + (uint32_t)st * STG * 4;
        const uint32_t bbase = abase + A_FLOATS * 4;
        const float* wrs = wb + (size_t)rs * CO * CI + c0;
#pragma unroll
        for (int t = 0; t < 4; t++) {                 // A: 128m x 32k
            int ci = tid + (t << 8);
            int m = ci >> 3, k4 = (ci & 7) << 2;
            uint32_t d = abase + (uint32_t)(m * AROW + k4) * 4;
            const float* g = wrs + m * CI + k4;
            asm volatile("cp.async.cg.shared.global [%0], [%1], 16;"
                         :: "r"(d), "l"(g) : "memory");
        }
#pragma unroll
        for (int t = 0; t < 8; t++) {                 // B: 256n x 32k, halo-masked
            int ci = tid + (t << 8);
            int n = ci >> 3, k4 = (ci & 7) << 2;
            int h = h4 + (n >> 6) + r, w = (n & 63) + s;
            bool ok = ((unsigned)h < 64u) && ((unsigned)w < 64u);
            int hc = ok ? h : 0, wc = ok ? w : 0;
            int sz = ok ? 16 : 0;
            uint32_t d = bbase + (uint32_t)(n * AROW + k4) * 4;
            const float* g = xb + (size_t)((hc << 6) + wc) * CI + c0 + k4;
            asm volatile("cp.async.cg.shared.global [%0], [%1], 16, %2;"
                         :: "r"(d), "l"(g), "r"(sz) : "memory");
        }
    };

    issue(0); asm volatile("cp.async.commit_group;" ::: "memory");
    issue(1); asm volatile("cp.async.commit_group;" ::: "memory");

    for (int it = 0; it < 36; ++it) {
        asm volatile("cp.async.wait_group 1;" ::: "memory");
        __syncthreads();
        if (it < 34) issue(it + 2);
        asm volatile("cp.async.commit_group;" ::: "memory");

        const int st = it % 3;
        const uint32_t abase = sb + (uint32_t)st * STG * 4;
        const uint32_t bbase = abase + A_FLOATS * 4;
        const uint32_t a0 = abase + (uint32_t)((mb + arow) * AROW + akh * 4) * 4;
        const uint32_t b0 = bbase + (uint32_t)((nb + brow) * AROW + bkh * 4) * 4;

#pragma unroll
        for (int ks = 0; ks < 4; ++ks) {
            uint32_t a[4][4], bq[4][4];
#pragma unroll
            for (int f = 0; f < 4; ++f)
                ldm_x4(a[f], a0 + (uint32_t)(f * 16 * AROW + ks * 8) * 4);
#pragma unroll
            for (int jj = 0; jj < 4; ++jj)
                ldm_x4(bq[jj], b0 + (uint32_t)(jj * 16 * AROW + ks * 8) * 4);
#pragma unroll
            for (int f = 0; f < 4; ++f)
#pragma unroll
                for (int jj = 0; jj < 4; ++jj) {
                    asm volatile(
                        "mma.sync.aligned.m16n8k8.row.col.f32.tf32.tf32.f32 "
                        "{%0,%1,%2,%3}, {%4,%5,%6,%7}, {%8,%9}, {%0,%1,%2,%3};"
                        : "+f"(acc[f][2 * jj][0]), "+f"(acc[f][2 * jj][1]),
                          "+f"(acc[f][2 * jj][2]), "+f"(acc[f][2 * jj][3])
                        : "r"(a[f][0]), "r"(a[f][1]), "r"(a[f][2]), "r"(a[f][3]),
                          "r"(bq[jj][0]), "r"(bq[jj][1]));
                    asm volatile(
                        "mma.sync.aligned.m16n8k8.row.col.f32.tf32.tf32.f32 "
                        "{%0,%1,%2,%3}, {%4,%5,%6,%7}, {%8,%9}, {%0,%1,%2,%3};"
                        : "+f"(acc[f][2 * jj + 1][0]), "+f"(acc[f][2 * jj + 1][1]),
                          "+f"(acc[f][2 * jj + 1][2]), "+f"(acc[f][2 * jj + 1][3])
                        : "r"(a[f][0]), "r"(a[f][1]), "r"(a[f][2]), "r"(a[f][3]),
                          "r"(bq[jj][2]), "r"(bq[jj][3]));
                }
        }
    }

    // epilogue: c0,c1 -> (row, 2 cols), c2,c3 -> (row+8, 2 cols)
#pragma unroll
    for (int f = 0; f < 4; ++f) {
        int co = mb + 16 * f + qid;
        float* o0 = out + ((size_t)(b * CO + co)) * HW + (nt << 8) + nb + 2 * tig;
        float* o1 = o0 + 8 * HW;
#pragma unroll
        for (int j = 0; j < 8; ++j) {
            *(float2*)(o0 + 8 * j) = make_float2(acc[f][j][0], acc[f][j][1]);
            *(float2*)(o1 + 8 * j) = make_float2(acc[f][j][2], acc[f][j][3]);
        }
    }
}

extern "C" void kernel_launch(void* const* d_in, const int* in_sizes, int n_in,
                              void* d_out, int out_size) {
    const float* feat = (const float*)d_in[0];   // (16,128,64,64)
    const float* wker = (const float*)d_in[1];   // (16,128,128,3,3)
    float* out = (float*)d_out;

    cudaFuncSetAttribute(conv_kernel, cudaFuncAttributeMaxDynamicSharedMemorySize, SMEM_BYTES);

    prep_w<<<dim3(16, BB), 256>>>(wker);
    prep_x<<<BB * 64, 256>>>(feat);
    conv_kernel<<<dim3(16, BB), 256, SMEM_BYTES>>>(out);
}

// round 6
// speedup vs baseline: 4.5920x; 1.4985x over previous
#include <cuda_runtime.h>
#include <cuda_fp16.h>
#include <cstdint>

// DynamicConvolution: B=16, Cin=Cout=128, K=3, H=W=64, pad=1, fp32.
// R6: fp16 mma.sync m16n8k16 implicit GEMM (R5 + A-tile cp.async index fix:
// m=ci>>2, seg=ci&3 — R5 left k16..31 of A uninitialized and overran into B).
// CTA = 128 cout x 256 spatial, 8 warps x (64x64), 3-stage cp.async, ldmatrix.

#define BB 16
#define CI 128
#define CO 128
#define HW 4096

__device__ __half g_xr[(size_t)BB * HW * CI];      // NHWC fp16 input (16 MB)
__device__ __half g_wt[(size_t)BB * 9 * CO * CI];  // [b][rs][cout][cin] fp16 (4.7 MB)

__device__ __forceinline__ uint32_t smem_u32(const void* p) {
    uint32_t a; asm("{ .reg .u64 t; cvta.to.shared.u64 t, %1; cvt.u32.u64 %0, t; }" : "=r"(a) : "l"(p));
    return a;
}
__device__ __forceinline__ void ldm_x4(uint32_t* r, uint32_t addr) {
    asm volatile("ldmatrix.sync.aligned.m8n8.x4.shared.b16 {%0,%1,%2,%3}, [%4];"
                 : "=r"(r[0]), "=r"(r[1]), "=r"(r[2]), "=r"(r[3]) : "r"(addr));
}

// ---- pre-pass: weights [b][cout][cin][rs] -> [b][rs][cout][cin], fp16 ----
__global__ __launch_bounds__(256) void prep_w(const float* __restrict__ w) {
    __shared__ float tw[8 * 1152];
    int cg = blockIdx.x, b = blockIdx.y;                 // cout group of 8
    const float* src = w + ((size_t)(b * CO + cg * 8)) * 1152;
    for (int i = threadIdx.x; i < 8 * 1152; i += 256) tw[i] = src[i];
    __syncthreads();
    for (int j = threadIdx.x; j < 8 * 1152; j += 256) {
        int rs = j >> 10, co8 = (j >> 7) & 7, cin = j & 127;
        g_wt[(((size_t)(b * 9 + rs)) * CO + cg * 8 + co8) * CI + cin] =
            __float2half(tw[co8 * 1152 + cin * 9 + rs]);
    }
}

// ---- pre-pass: input NCHW -> NHWC, fp16 ----
__global__ __launch_bounds__(256) void prep_x(const float* __restrict__ x) {
    __shared__ float t[64][129];
    int b = blockIdx.x >> 6, h = blockIdx.x & 63;
    const float* src = x + (size_t)b * CI * HW + h * 64;
    for (int c0 = 0; c0 < CI; c0 += 4) {
        int c = c0 + (threadIdx.x >> 6), w = threadIdx.x & 63;
        t[w][c] = src[(size_t)c * HW + w];
    }
    __syncthreads();
    __half* dst = g_xr + ((size_t)b * 64 + h) * 64 * CI;
    for (int w0 = 0; w0 < 64; w0 += 2) {
        int w = w0 + (threadIdx.x >> 7), c = threadIdx.x & 127;
        dst[(size_t)w * CI + c] = __float2half(t[w][c]);
    }
}

// ---- main conv ----
static constexpr int AP = 40;                          // 32 halves + 8 pad (80 B rows)
static constexpr int A_HALVES = 128 * AP;              // 5120 (10240 B)
static constexpr int B_HALVES = 256 * AP;              // 10240 (20480 B)
static constexpr int STG = A_HALVES + B_HALVES;        // 15360 halves / stage
static constexpr int SMEM_BYTES = 3 * STG * 2;         // 92160

__global__ __launch_bounds__(256, 1) void conv_kernel(float* __restrict__ out) {
    extern __shared__ __half sm[];
    const uint32_t sb = smem_u32(sm);
    const int tid = threadIdx.x, wid = tid >> 5, lane = tid & 31;
    const int b = blockIdx.y, nt = blockIdx.x;
    const int h4 = nt << 2;                            // 4 image rows / CTA
    const int mb = (wid & 1) << 6, nb = (wid >> 1) << 6;
    const int qid = lane >> 2, tig = lane & 3;

    // ldmatrix lane->address selects
    const int ar16 = ((lane >> 3) & 1) * 8 + (lane & 7);   // A: row-in-16
    const int akh  = (lane >> 4) & 1;                      // A: k-half (0/8)
    const int br16 = ((lane >> 4) & 1) * 8 + (lane & 7);   // B: n-in-16
    const int bkh  = (lane >> 3) & 1;                      // B: k-half

    const __half* xb = g_xr + (size_t)b * HW * CI;
    const __half* wb = g_wt + (size_t)b * 9 * CO * CI;

    float acc[4][8][4];
#pragma unroll
    for (int f = 0; f < 4; f++)
#pragma unroll
        for (int j = 0; j < 8; j++)
#pragma unroll
            for (int c = 0; c < 4; c++) acc[f][j][c] = 0.f;

    auto issue = [&](int it) {
        const int st = it % 3, rs = it >> 2, c0 = (it & 3) << 5;   // cin chunk of 32
        const int rd = rs / 3, r = rd - 1, s = rs - rd * 3 - 1;
        const uint32_t abase = sb + (uint32_t)st * STG * 2;
        const uint32_t bbase = abase + A_HALVES * 2;
        const __half* wrs = wb + (size_t)rs * CO * CI + c0;
#pragma unroll
        for (int t = 0; t < 2; t++) {                  // A: 128m x 32k halves (512 x 16B)
            int ci = tid + (t << 8);
            int m = ci >> 2, seg = ci & 3;             // 4 x 16B per 64B row
            uint32_t d = abase + (uint32_t)(m * AP + seg * 8) * 2;
            const __half* g = wrs + m * CI + seg * 8;
            asm volatile("cp.async.cg.shared.global [%0], [%1], 16;"
                         :: "r"(d), "l"(g) : "memory");
        }
#pragma unroll
        for (int t = 0; t < 4; t++) {                  // B: 256n x 32k, halo-masked
            int ci = tid + (t << 8);
            int n = ci >> 2, seg = ci & 3;             // 4 x 16B per 64B row
            int h = h4 + (n >> 6) + r, w = (n & 63) + s;
            bool ok = ((unsigned)h < 64u) && ((unsigned)w < 64u);
            int hc = ok ? h : 0, wc = ok ? w : 0;
            int sz = ok ? 16 : 0;
            uint32_t d = bbase + (uint32_t)(n * AP + seg * 8) * 2;
            const __half* g = xb + (size_t)((hc << 6) + wc) * CI + c0 + seg * 8;
            asm volatile("cp.async.cg.shared.global [%0], [%1], 16, %2;"
                         :: "r"(d), "l"(g), "r"(sz) : "memory");
        }
    };

    issue(0); asm volatile("cp.async.commit_group;" ::: "memory");
    issue(1); asm volatile("cp.async.commit_group;" ::: "memory");

    for (int it = 0; it < 36; ++it) {
        asm volatile("cp.async.wait_group 1;" ::: "memory");
        __syncthreads();
        if (it < 34) issue(it + 2);
        asm volatile("cp.async.commit_group;" ::: "memory");

        const int st = it % 3;
        const uint32_t abase = sb + (uint32_t)st * STG * 2;
        const uint32_t bbase = abase + A_HALVES * 2;
        const uint32_t a0 = abase + (uint32_t)((mb + ar16) * AP + akh * 8) * 2;
        const uint32_t b0 = bbase + (uint32_t)((nb + br16) * AP + bkh * 8) * 2;

#pragma unroll
        for (int ks = 0; ks < 2; ++ks) {               // two k16 slices
            uint32_t a[4][4], bq[4][4];
#pragma unroll
            for (int f = 0; f < 4; ++f)
                ldm_x4(a[f], a0 + (uint32_t)(f * 16 * AP + ks * 16) * 2);
#pragma unroll
            for (int jj = 0; jj < 4; ++jj)
                ldm_x4(bq[jj], b0 + (uint32_t)(jj * 16 * AP + ks * 16) * 2);
#pragma unroll
            for (int f = 0; f < 4; ++f)
#pragma unroll
                for (int jj = 0; jj < 4; ++jj) {
                    asm volatile(
                        "mma.sync.aligned.m16n8k16.row.col.f32.f16.f16.f32 "
                        "{%0,%1,%2,%3}, {%4,%5,%6,%7}, {%8,%9}, {%0,%1,%2,%3};"
                        : "+f"(acc[f][2 * jj][0]), "+f"(acc[f][2 * jj][1]),
                          "+f"(acc[f][2 * jj][2]), "+f"(acc[f][2 * jj][3])
                        : "r"(a[f][0]), "r"(a[f][1]), "r"(a[f][2]), "r"(a[f][3]),
                          "r"(bq[jj][0]), "r"(bq[jj][1]));
                    asm volatile(
                        "mma.sync.aligned.m16n8k16.row.col.f32.f16.f16.f32 "
                        "{%0,%1,%2,%3}, {%4,%5,%6,%7}, {%8,%9}, {%0,%1,%2,%3};"
                        : "+f"(acc[f][2 * jj + 1][0]), "+f"(acc[f][2 * jj + 1][1]),
                          "+f"(acc[f][2 * jj + 1][2]), "+f"(acc[f][2 * jj + 1][3])
                        : "r"(a[f][0]), "r"(a[f][1]), "r"(a[f][2]), "r"(a[f][3]),
                          "r"(bq[jj][2]), "r"(bq[jj][3]));
                }
        }
    }

    // epilogue: c0,c1 -> (row, 2 cols), c2,c3 -> (row+8, 2 cols)
#pragma unroll
    for (int f = 0; f < 4; ++f) {
        int co = mb + 16 * f + qid;
        float* o0 = out + ((size_t)(b * CO + co)) * HW + (nt << 8) + nb + 2 * tig;
        float* o1 = o0 + 8 * HW;
#pragma unroll
        for (int j = 0; j < 8; ++j) {
            *(float2*)(o0 + 8 * j) = make_float2(acc[f][j][0], acc[f][j][1]);
            *(float2*)(o1 + 8 * j) = make_float2(acc[f][j][2], acc[f][j][3]);
        }
    }
}

extern "C" void kernel_launch(void* const* d_in, const int* in_sizes, int n_in,
                              void* d_out, int out_size) {
    const float* feat = (const float*)d_in[0];   // (16,128,64,64)
    const float* wker = (const float*)d_in[1];   // (16,128,128,3,3)
    float* out = (float*)d_out;

    cudaFuncSetAttribute(conv_kernel, cudaFuncAttributeMaxDynamicSharedMemorySize, SMEM_BYTES);

    prep_w<<<dim3(16, BB), 256>>>(wker);
    prep_x<<<BB * 64, 256>>>(feat);
    conv_kernel<<<dim3(16, BB), 256, SMEM_BYTES>>>(out);
}

// round 7
// speedup vs baseline: 4.7104x; 1.0258x over previous
#include <cuda_runtime.h>
#include <cuda_fp16.h>
#include <cstdint>

// DynamicConvolution: B=16, Cin=Cout=128, K=3, H=W=64, pad=1, fp32.
// R7: R6 conv (fp16 m16n8k16, 3-stage cp.async, ldmatrix) + fused single-launch
// pre-pass (weight repack->fp16 and NCHW->NHWC fp16 in one 1280-block grid).

#define BB 16
#define CI 128
#define CO 128
#define HW 4096

__device__ __half g_xr[(size_t)BB * HW * CI];      // NHWC fp16 input (16 MB)
__device__ __half g_wt[(size_t)BB * 9 * CO * CI];  // [b][rs][cout][cin] fp16 (4.7 MB)

__device__ __forceinline__ uint32_t smem_u32(const void* p) {
    uint32_t a; asm("{ .reg .u64 t; cvta.to.shared.u64 t, %1; cvt.u32.u64 %0, t; }" : "=r"(a) : "l"(p));
    return a;
}
__device__ __forceinline__ void ldm_x4(uint32_t* r, uint32_t addr) {
    asm volatile("ldmatrix.sync.aligned.m8n8.x4.shared.b16 {%0,%1,%2,%3}, [%4];"
                 : "=r"(r[0]), "=r"(r[1]), "=r"(r[2]), "=r"(r[3]) : "r"(addr));
}

// ---- fused pre-pass ----
// blocks [0,1024):  input NCHW -> NHWC fp16, block = (b, h)
// blocks [1024,1280): weights [b][cout][cin][rs] -> [b][rs][cout][cin] fp16
__global__ __launch_bounds__(256) void prep_fused(const float* __restrict__ x,
                                                  const float* __restrict__ w) {
    __shared__ char buf[36864];
    if (blockIdx.x < 1024) {
        float (*t)[129] = (float(*)[129])buf;               // 64*129*4 = 33024 B
        int b = blockIdx.x >> 6, h = blockIdx.x & 63;
        const float* src = x + (size_t)b * CI * HW + h * 64;
        for (int c0 = 0; c0 < CI; c0 += 4) {
            int c = c0 + (threadIdx.x >> 6), wpos = threadIdx.x & 63;
            t[wpos][c] = src[(size_t)c * HW + wpos];
        }
        __syncthreads();
        __half* dst = g_xr + ((size_t)b * 64 + h) * 64 * CI;
        for (int w0 = 0; w0 < 64; w0 += 2) {
            int wpos = w0 + (threadIdx.x >> 7), c = threadIdx.x & 127;
            dst[(size_t)wpos * CI + c] = __float2half(t[wpos][c]);
        }
    } else {
        float* tw = (float*)buf;                            // 8*1152*4 = 36864 B
        int idx = blockIdx.x - 1024;
        int cg = idx & 15, b = idx >> 4;                    // cout group of 8
        const float* src = w + ((size_t)(b * CO + cg * 8)) * 1152;
        for (int i = threadIdx.x; i < 8 * 1152; i += 256) tw[i] = src[i];
        __syncthreads();
        for (int j = threadIdx.x; j < 8 * 1152; j += 256) {
            int rs = j >> 10, co8 = (j >> 7) & 7, cin = j & 127;
            g_wt[(((size_t)(b * 9 + rs)) * CO + cg * 8 + co8) * CI + cin] =
                __float2half(tw[co8 * 1152 + cin * 9 + rs]);
        }
    }
}

// ---- main conv ----
static constexpr int AP = 40;                          // 32 halves + 8 pad (80 B rows)
static constexpr int A_HALVES = 128 * AP;              // 5120 (10240 B)
static constexpr int B_HALVES = 256 * AP;              // 10240 (20480 B)
static constexpr int STG = A_HALVES + B_HALVES;        // 15360 halves / stage
static constexpr int SMEM_BYTES = 3 * STG * 2;         // 92160

__global__ __launch_bounds__(256, 1) void conv_kernel(float* __restrict__ out) {
    extern __shared__ __half sm[];
    const uint32_t sb = smem_u32(sm);
    const int tid = threadIdx.x, wid = tid >> 5, lane = tid & 31;
    const int b = blockIdx.y, nt = blockIdx.x;
    const int h4 = nt << 2;                            // 4 image rows / CTA
    const int mb = (wid & 1) << 6, nb = (wid >> 1) << 6;
    const int qid = lane >> 2, tig = lane & 3;

    const int ar16 = ((lane >> 3) & 1) * 8 + (lane & 7);   // A: row-in-16
    const int akh  = (lane >> 4) & 1;                      // A: k-half
    const int br16 = ((lane >> 4) & 1) * 8 + (lane & 7);   // B: n-in-16
    const int bkh  = (lane >> 3) & 1;                      // B: k-half

    const __half* xb = g_xr + (size_t)b * HW * CI;
    const __half* wb = g_wt + (size_t)b * 9 * CO * CI;

    float acc[4][8][4];
#pragma unroll
    for (int f = 0; f < 4; f++)
#pragma unroll
        for (int j = 0; j < 8; j++)
#pragma unroll
            for (int c = 0; c < 4; c++) acc[f][j][c] = 0.f;

    auto issue = [&](int it) {
        const int st = it % 3, rs = it >> 2, c0 = (it & 3) << 5;   // cin chunk of 32
        const int rd = rs / 3, r = rd - 1, s = rs - rd * 3 - 1;
        const uint32_t abase = sb + (uint32_t)st * STG * 2;
        const uint32_t bbase = abase + A_HALVES * 2;
        const __half* wrs = wb + (size_t)rs * CO * CI + c0;
#pragma unroll
        for (int t = 0; t < 2; t++) {                  // A: 128m x 32k (512 x 16B)
            int ci = tid + (t << 8);
            int m = ci >> 2, seg = ci & 3;
            uint32_t d = abase + (uint32_t)(m * AP + seg * 8) * 2;
            const __half* g = wrs + m * CI + seg * 8;
            asm volatile("cp.async.cg.shared.global [%0], [%1], 16;"
                         :: "r"(d), "l"(g) : "memory");
        }
#pragma unroll
        for (int t = 0; t < 4; t++) {                  // B: 256n x 32k, halo-masked
            int ci = tid + (t << 8);
            int n = ci >> 2, seg = ci & 3;
            int h = h4 + (n >> 6) + r, w = (n & 63) + s;
            bool ok = ((unsigned)h < 64u) && ((unsigned)w < 64u);
            int hc = ok ? h : 0, wc = ok ? w : 0;
            int sz = ok ? 16 : 0;
            uint32_t d = bbase + (uint32_t)(n * AP + seg * 8) * 2;
            const __half* g = xb + (size_t)((hc << 6) + wc) * CI + c0 + seg * 8;
            asm volatile("cp.async.cg.shared.global [%0], [%1], 16, %2;"
                         :: "r"(d), "l"(g), "r"(sz) : "memory");
        }
    };

    issue(0); asm volatile("cp.async.commit_group;" ::: "memory");
    issue(1); asm volatile("cp.async.commit_group;" ::: "memory");

    for (int it = 0; it < 36; ++it) {
        asm volatile("cp.async.wait_group 1;" ::: "memory");
        __syncthreads();
        if (it < 34) issue(it + 2);
        asm volatile("cp.async.commit_group;" ::: "memory");

        const int st = it % 3;
        const uint32_t abase = sb + (uint32_t)st * STG * 2;
        const uint32_t bbase = abase + A_HALVES * 2;
        const uint32_t a0 = abase + (uint32_t)((mb + ar16) * AP + akh * 8) * 2;
        const uint32_t b0 = bbase + (uint32_t)((nb + br16) * AP + bkh * 8) * 2;

#pragma unroll
        for (int ks = 0; ks < 2; ++ks) {               // two k16 slices
            uint32_t a[4][4], bq[4][4];
#pragma unroll
            for (int f = 0; f < 4; ++f)
                ldm_x4(a[f], a0 + (uint32_t)(f * 16 * AP + ks * 16) * 2);
#pragma unroll
            for (int jj = 0; jj < 4; ++jj)
                ldm_x4(bq[jj], b0 + (uint32_t)(jj * 16 * AP + ks * 16) * 2);
#pragma unroll
            for (int f = 0; f < 4; ++f)
#pragma unroll
                for (int jj = 0; jj < 4; ++jj) {
                    asm volatile(
                        "mma.sync.aligned.m16n8k16.row.col.f32.f16.f16.f32 "
                        "{%0,%1,%2,%3}, {%4,%5,%6,%7}, {%8,%9}, {%0,%1,%2,%3};"
                        : "+f"(acc[f][2 * jj][0]), "+f"(acc[f][2 * jj][1]),
                          "+f"(acc[f][2 * jj][2]), "+f"(acc[f][2 * jj][3])
                        : "r"(a[f][0]), "r"(a[f][1]), "r"(a[f][2]), "r"(a[f][3]),
                          "r"(bq[jj][0]), "r"(bq[jj][1]));
                    asm volatile(
                        "mma.sync.aligned.m16n8k16.row.col.f32.f16.f16.f32 "
                        "{%0,%1,%2,%3}, {%4,%5,%6,%7}, {%8,%9}, {%0,%1,%2,%3};"
                        : "+f"(acc[f][2 * jj + 1][0]), "+f"(acc[f][2 * jj + 1][1]),
                          "+f"(acc[f][2 * jj + 1][2]), "+f"(acc[f][2 * jj + 1][3])
                        : "r"(a[f][0]), "r"(a[f][1]), "r"(a[f][2]), "r"(a[f][3]),
                          "r"(bq[jj][2]), "r"(bq[jj][3]));
                }
        }
    }

    // epilogue
#pragma unroll
    for (int f = 0; f < 4; ++f) {
        int co = mb + 16 * f + qid;
        float* o0 = out + ((size_t)(b * CO + co)) * HW + (nt << 8) + nb + 2 * tig;
        float* o1 = o0 + 8 * HW;
#pragma unroll
        for (int j = 0; j < 8; ++j) {
            *(float2*)(o0 + 8 * j) = make_float2(acc[f][j][0], acc[f][j][1]);
            *(float2*)(o1 + 8 * j) = make_float2(acc[f][j][2], acc[f][j][3]);
        }
    }
}

extern "C" void kernel_launch(void* const* d_in, const int* in_sizes, int n_in,
                              void* d_out, int out_size) {
    const float* feat = (const float*)d_in[0];   // (16,128,64,64)
    const float* wker = (const float*)d_in[1];   // (16,128,128,3,3)
    float* out = (float*)d_out;

    cudaFuncSetAttribute(conv_kernel, cudaFuncAttributeMaxDynamicSharedMemorySize, SMEM_BYTES);

    prep_fused<<<1280, 256>>>(feat, wker);
    conv_kernel<<<dim3(16, BB), 256, SMEM_BYTES>>>(out);
}

// round 8
// speedup vs baseline: 5.1368x; 1.0905x over previous
#include <cuda_runtime.h>
#include <cuda_fp16.h>
#include <cstdint>

// DynamicConvolution: B=16, Cin=Cout=128, K=3, H=W=64, pad=1, fp32.
// R8: R7 + 512 threads/CTA (16 warps, warp tile 64x32) to lift tensor-pipe
// occupancy from 2 to 4 warps/SMSP. CTA tile 128 cout x 256 spatial unchanged.

#define BB 16
#define CI 128
#define CO 128
#define HW 4096

__device__ __half g_xr[(size_t)BB * HW * CI];      // NHWC fp16 input (16 MB)
__device__ __half g_wt[(size_t)BB * 9 * CO * CI];  // [b][rs][cout][cin] fp16 (4.7 MB)

__device__ __forceinline__ uint32_t smem_u32(const void* p) {
    uint32_t a; asm("{ .reg .u64 t; cvta.to.shared.u64 t, %1; cvt.u32.u64 %0, t; }" : "=r"(a) : "l"(p));
    return a;
}
__device__ __forceinline__ void ldm_x4(uint32_t* r, uint32_t addr) {
    asm volatile("ldmatrix.sync.aligned.m8n8.x4.shared.b16 {%0,%1,%2,%3}, [%4];"
                 : "=r"(r[0]), "=r"(r[1]), "=r"(r[2]), "=r"(r[3]) : "r"(addr));
}

// ---- fused pre-pass ----
__global__ __launch_bounds__(256) void prep_fused(const float* __restrict__ x,
                                                  const float* __restrict__ w) {
    __shared__ char buf[36864];
    if (blockIdx.x < 1024) {
        float (*t)[129] = (float(*)[129])buf;
        int b = blockIdx.x >> 6, h = blockIdx.x & 63;
        const float* src = x + (size_t)b * CI * HW + h * 64;
        for (int c0 = 0; c0 < CI; c0 += 4) {
            int c = c0 + (threadIdx.x >> 6), wpos = threadIdx.x & 63;
            t[wpos][c] = src[(size_t)c * HW + wpos];
        }
        __syncthreads();
        __half* dst = g_xr + ((size_t)b * 64 + h) * 64 * CI;
        for (int w0 = 0; w0 < 64; w0 += 2) {
            int wpos = w0 + (threadIdx.x >> 7), c = threadIdx.x & 127;
            dst[(size_t)wpos * CI + c] = __float2half(t[wpos][c]);
        }
    } else {
        float* tw = (float*)buf;
        int idx = blockIdx.x - 1024;
        int cg = idx & 15, b = idx >> 4;
        const float* src = w + ((size_t)(b * CO + cg * 8)) * 1152;
        for (int i = threadIdx.x; i < 8 * 1152; i += 256) tw[i] = src[i];
        __syncthreads();
        for (int j = threadIdx.x; j < 8 * 1152; j += 256) {
            int rs = j >> 10, co8 = (j >> 7) & 7, cin = j & 127;
            g_wt[(((size_t)(b * 9 + rs)) * CO + cg * 8 + co8) * CI + cin] =
                __float2half(tw[co8 * 1152 + cin * 9 + rs]);
        }
    }
}

// ---- main conv ----
static constexpr int AP = 40;                          // 32 halves + 8 pad (80 B rows)
static constexpr int A_HALVES = 128 * AP;              // 5120 (10240 B)
static constexpr int B_HALVES = 256 * AP;              // 10240 (20480 B)
static constexpr int STG = A_HALVES + B_HALVES;        // 15360 halves / stage
static constexpr int SMEM_BYTES = 3 * STG * 2;         // 92160

__global__ __launch_bounds__(512, 1) void conv_kernel(float* __restrict__ out) {
    extern __shared__ __half sm[];
    const uint32_t sb = smem_u32(sm);
    const int tid = threadIdx.x, wid = tid >> 5, lane = tid & 31;
    const int b = blockIdx.y, nt = blockIdx.x;
    const int h4 = nt << 2;                            // 4 image rows / CTA
    const int mb = (wid & 1) << 6;                     // warp grid: 2 m x 8 n
    const int nb = (wid >> 1) << 5;                    // warp tile 64 x 32
    const int qid = lane >> 2, tig = lane & 3;

    const int ar16 = ((lane >> 3) & 1) * 8 + (lane & 7);   // A: row-in-16
    const int akh  = (lane >> 4) & 1;                      // A: k-half
    const int br16 = ((lane >> 4) & 1) * 8 + (lane & 7);   // B: n-in-16
    const int bkh  = (lane >> 3) & 1;                      // B: k-half

    const __half* xb = g_xr + (size_t)b * HW * CI;
    const __half* wb = g_wt + (size_t)b * 9 * CO * CI;

    float acc[4][4][4];                                // 4 m16 x 4 n8 x 4
#pragma unroll
    for (int f = 0; f < 4; f++)
#pragma unroll
        for (int j = 0; j < 4; j++)
#pragma unroll
            for (int c = 0; c < 4; c++) acc[f][j][c] = 0.f;

    auto issue = [&](int it) {
        const int st = it % 3, rs = it >> 2, c0 = (it & 3) << 5;   // cin chunk of 32
        const int rd = rs / 3, r = rd - 1, s = rs - rd * 3 - 1;
        const uint32_t abase = sb + (uint32_t)st * STG * 2;
        const uint32_t bbase = abase + A_HALVES * 2;
        const __half* wrs = wb + (size_t)rs * CO * CI + c0;
        {                                              // A: 128m x 32k = 512 x 16B
            int m = tid >> 2, seg = tid & 3;
            uint32_t d = abase + (uint32_t)(m * AP + seg * 8) * 2;
            const __half* g = wrs + m * CI + seg * 8;
            asm volatile("cp.async.cg.shared.global [%0], [%1], 16;"
                         :: "r"(d), "l"(g) : "memory");
        }
#pragma unroll
        for (int t = 0; t < 2; t++) {                  // B: 256n x 32k, halo-masked
            int ci = tid + (t << 9);
            int n = ci >> 2, seg = ci & 3;
            int h = h4 + (n >> 6) + r, w = (n & 63) + s;
            bool ok = ((unsigned)h < 64u) && ((unsigned)w < 64u);
            int hc = ok ? h : 0, wc = ok ? w : 0;
            int sz = ok ? 16 : 0;
            uint32_t d = bbase + (uint32_t)(n * AP + seg * 8) * 2;
            const __half* g = xb + (size_t)((hc << 6) + wc) * CI + c0 + seg * 8;
            asm volatile("cp.async.cg.shared.global [%0], [%1], 16, %2;"
                         :: "r"(d), "l"(g), "r"(sz) : "memory");
        }
    };

    issue(0); asm volatile("cp.async.commit_group;" ::: "memory");
    issue(1); asm volatile("cp.async.commit_group;" ::: "memory");

    for (int it = 0; it < 36; ++it) {
        asm volatile("cp.async.wait_group 1;" ::: "memory");
        __syncthreads();
        if (it < 34) issue(it + 2);
        asm volatile("cp.async.commit_group;" ::: "memory");

        const int st = it % 3;
        const uint32_t abase = sb + (uint32_t)st * STG * 2;
        const uint32_t bbase = abase + A_HALVES * 2;
        const uint32_t a0 = abase + (uint32_t)((mb + ar16) * AP + akh * 8) * 2;
        const uint32_t b0 = bbase + (uint32_t)((nb + br16) * AP + bkh * 8) * 2;

#pragma unroll
        for (int ks = 0; ks < 2; ++ks) {               // two k16 slices
            uint32_t a[4][4], bq[2][4];
#pragma unroll
            for (int f = 0; f < 4; ++f)
                ldm_x4(a[f], a0 + (uint32_t)(f * 16 * AP + ks * 16) * 2);
#pragma unroll
            for (int jj = 0; jj < 2; ++jj)
                ldm_x4(bq[jj], b0 + (uint32_t)(jj * 16 * AP + ks * 16) * 2);
#pragma unroll
            for (int f = 0; f < 4; ++f)
#pragma unroll
                for (int jj = 0; jj < 2; ++jj) {
                    asm volatile(
                        "mma.sync.aligned.m16n8k16.row.col.f32.f16.f16.f32 "
                        "{%0,%1,%2,%3}, {%4,%5,%6,%7}, {%8,%9}, {%0,%1,%2,%3};"
                        : "+f"(acc[f][2 * jj][0]), "+f"(acc[f][2 * jj][1]),
                          "+f"(acc[f][2 * jj][2]), "+f"(acc[f][2 * jj][3])
                        : "r"(a[f][0]), "r"(a[f][1]), "r"(a[f][2]), "r"(a[f][3]),
                          "r"(bq[jj][0]), "r"(bq[jj][1]));
                    asm volatile(
                        "mma.sync.aligned.m16n8k16.row.col.f32.f16.f16.f32 "
                        "{%0,%1,%2,%3}, {%4,%5,%6,%7}, {%8,%9}, {%0,%1,%2,%3};"
                        : "+f"(acc[f][2 * jj + 1][0]), "+f"(acc[f][2 * jj + 1][1]),
                          "+f"(acc[f][2 * jj + 1][2]), "+f"(acc[f][2 * jj + 1][3])
                        : "r"(a[f][0]), "r"(a[f][1]), "r"(a[f][2]), "r"(a[f][3]),
                          "r"(bq[jj][2]), "r"(bq[jj][3]));
                }
        }
    }

    // epilogue: warp covers 64 m x 32 n
#pragma unroll
    for (int f = 0; f < 4; ++f) {
        int co = mb + 16 * f + qid;
        float* o0 = out + ((size_t)(b * CO + co)) * HW + (nt << 8) + nb + 2 * tig;
        float* o1 = o0 + 8 * HW;
#pragma unroll
        for (int j = 0; j < 4; ++j) {
            *(float2*)(o0 + 8 * j) = make_float2(acc[f][j][0], acc[f][j][1]);
            *(float2*)(o1 + 8 * j) = make_float2(acc[f][j][2], acc[f][j][3]);
        }
    }
}

extern "C" void kernel_launch(void* const* d_in, const int* in_sizes, int n_in,
                              void* d_out, int out_size) {
    const float* feat = (const float*)d_in[0];   // (16,128,64,64)
    const float* wker = (const float*)d_in[1];   // (16,128,128,3,3)
    float* out = (float*)d_out;

    cudaFuncSetAttribute(conv_kernel, cudaFuncAttributeMaxDynamicSharedMemorySize, SMEM_BYTES);

    prep_fused<<<1280, 256>>>(feat, wker);
    conv_kernel<<<dim3(16, BB), 512, SMEM_BYTES>>>(out);
}

// round 9
// speedup vs baseline: 5.5663x; 1.0836x over previous
#include <cuda_runtime.h>
#include <cuda_fp16.h>
#include <cstdint>

// DynamicConvolution: B=16, Cin=Cout=128, K=3, H=W=64, pad=1, fp32.
// R9: 2 CTAs/SM (256 thr, 128x128 tile), K-chunk 64, 3-stage cp.async,
// fp16 m16n8k16 + ldmatrix. Two independent barrier domains per SM.

#define BB 16
#define CI 128
#define CO 128
#define HW 4096

__device__ __half g_xr[(size_t)BB * HW * CI];      // NHWC fp16 input (16 MB)
__device__ __half g_wt[(size_t)BB * 9 * CO * CI];  // [b][rs][cout][cin] fp16 (4.7 MB)

__device__ __forceinline__ uint32_t smem_u32(const void* p) {
    uint32_t a; asm("{ .reg .u64 t; cvta.to.shared.u64 t, %1; cvt.u32.u64 %0, t; }" : "=r"(a) : "l"(p));
    return a;
}
__device__ __forceinline__ void ldm_x4(uint32_t* r, uint32_t addr) {
    asm volatile("ldmatrix.sync.aligned.m8n8.x4.shared.b16 {%0,%1,%2,%3}, [%4];"
                 : "=r"(r[0]), "=r"(r[1]), "=r"(r[2]), "=r"(r[3]) : "r"(addr));
}

// ---- fused pre-pass (unchanged from R7/R8) ----
__global__ __launch_bounds__(256) void prep_fused(const float* __restrict__ x,
                                                  const float* __restrict__ w) {
    __shared__ char buf[36864];
    if (blockIdx.x < 1024) {
        float (*t)[129] = (float(*)[129])buf;
        int b = blockIdx.x >> 6, h = blockIdx.x & 63;
        const float* src = x + (size_t)b * CI * HW + h * 64;
        for (int c0 = 0; c0 < CI; c0 += 4) {
            int c = c0 + (threadIdx.x >> 6), wpos = threadIdx.x & 63;
            t[wpos][c] = src[(size_t)c * HW + wpos];
        }
        __syncthreads();
        __half* dst = g_xr + ((size_t)b * 64 + h) * 64 * CI;
        for (int w0 = 0; w0 < 64; w0 += 2) {
            int wpos = w0 + (threadIdx.x >> 7), c = threadIdx.x & 127;
            dst[(size_t)wpos * CI + c] = __float2half(t[wpos][c]);
        }
    } else {
        float* tw = (float*)buf;
        int idx = blockIdx.x - 1024;
        int cg = idx & 15, b = idx >> 4;
        const float* src = w + ((size_t)(b * CO + cg * 8)) * 1152;
        for (int i = threadIdx.x; i < 8 * 1152; i += 256) tw[i] = src[i];
        __syncthreads();
        for (int j = threadIdx.x; j < 8 * 1152; j += 256) {
            int rs = j >> 10, co8 = (j >> 7) & 7, cin = j & 127;
            g_wt[(((size_t)(b * 9 + rs)) * CO + cg * 8 + co8) * CI + cin] =
                __float2half(tw[co8 * 1152 + cin * 9 + rs]);
        }
    }
}

// ---- main conv ----
static constexpr int AP = 72;                          // 64 halves + 8 pad (144 B rows)
static constexpr int A_HALVES = 128 * AP;              // 9216
static constexpr int B_HALVES = 128 * AP;              // 9216
static constexpr int STG = A_HALVES + B_HALVES;        // 18432 halves (36864 B)
static constexpr int SMEM_BYTES = 3 * STG * 2;         // 110592 B / CTA

__global__ __launch_bounds__(256, 2) void conv_kernel(float* __restrict__ out) {
    extern __shared__ __half sm[];
    const uint32_t sb = smem_u32(sm);
    const int tid = threadIdx.x, wid = tid >> 5, lane = tid & 31;
    const int b = blockIdx.y, nt = blockIdx.x;
    const int h2 = nt << 1;                            // 2 image rows / CTA
    const int mb = (wid & 1) << 6;                     // warp grid: 2 m x 4 n
    const int nb = (wid >> 1) << 5;                    // warp tile 64 x 32
    const int qid = lane >> 2, tig = lane & 3;

    const int ar16 = ((lane >> 3) & 1) * 8 + (lane & 7);   // A: row-in-16
    const int akh  = (lane >> 4) & 1;                      // A: k-half
    const int br16 = ((lane >> 4) & 1) * 8 + (lane & 7);   // B: n-in-16
    const int bkh  = (lane >> 3) & 1;                      // B: k-half

    const __half* xb = g_xr + (size_t)b * HW * CI;
    const __half* wb = g_wt + (size_t)b * 9 * CO * CI;

    float acc[4][4][4];                                // 4 m16 x 4 n8 x 4
#pragma unroll
    for (int f = 0; f < 4; f++)
#pragma unroll
        for (int j = 0; j < 4; j++)
#pragma unroll
            for (int c = 0; c < 4; c++) acc[f][j][c] = 0.f;

    auto issue = [&](int it) {
        const int st = it % 3, rs = it >> 1, c0 = (it & 1) << 6;   // cin chunk of 64
        const int rd = rs / 3, r = rd - 1, s = rs - rd * 3 - 1;
        const uint32_t abase = sb + (uint32_t)st * STG * 2;
        const uint32_t bbase = abase + A_HALVES * 2;
        const __half* wrs = wb + (size_t)rs * CO * CI + c0;
#pragma unroll
        for (int t = 0; t < 4; t++) {                  // A: 128m x 64k = 1024 x 16B
            int ci = tid + (t << 8);
            int m = ci >> 3, seg = ci & 7;
            uint32_t d = abase + (uint32_t)(m * AP + seg * 8) * 2;
            const __half* g = wrs + m * CI + seg * 8;
            asm volatile("cp.async.cg.shared.global [%0], [%1], 16;"
                         :: "r"(d), "l"(g) : "memory");
        }
#pragma unroll
        for (int t = 0; t < 4; t++) {                  // B: 128n x 64k, halo-masked
            int ci = tid + (t << 8);
            int n = ci >> 3, seg = ci & 7;
            int h = h2 + (n >> 6) + r, w = (n & 63) + s;
            bool ok = ((unsigned)h < 64u) && ((unsigned)w < 64u);
            int hc = ok ? h : 0, wc = ok ? w : 0;
            int sz = ok ? 16 : 0;
            uint32_t d = bbase + (uint32_t)(n * AP + seg * 8) * 2;
            const __half* g = xb + (size_t)((hc << 6) + wc) * CI + c0 + seg * 8;
            asm volatile("cp.async.cg.shared.global [%0], [%1], 16, %2;"
                         :: "r"(d), "l"(g), "r"(sz) : "memory");
        }
    };

    issue(0); asm volatile("cp.async.commit_group;" ::: "memory");
    issue(1); asm volatile("cp.async.commit_group;" ::: "memory");

    for (int it = 0; it < 18; ++it) {
        asm volatile("cp.async.wait_group 1;" ::: "memory");
        __syncthreads();
        if (it < 16) issue(it + 2);
        asm volatile("cp.async.commit_group;" ::: "memory");

        const int st = it % 3;
        const uint32_t abase = sb + (uint32_t)st * STG * 2;
        const uint32_t bbase = abase + A_HALVES * 2;
        const uint32_t a0 = abase + (uint32_t)((mb + ar16) * AP + akh * 8) * 2;
        const uint32_t b0 = bbase + (uint32_t)((nb + br16) * AP + bkh * 8) * 2;

#pragma unroll
        for (int ks = 0; ks < 4; ++ks) {               // four k16 slices
            uint32_t a[4][4], bq[2][4];
#pragma unroll
            for (int f = 0; f < 4; ++f)
                ldm_x4(a[f], a0 + (uint32_t)(f * 16 * AP + ks * 16) * 2);
#pragma unroll
            for (int jj = 0; jj < 2; ++jj)
                ldm_x4(bq[jj], b0 + (uint32_t)(jj * 16 * AP + ks * 16) * 2);
#pragma unroll
            for (int f = 0; f < 4; ++f)
#pragma unroll
                for (int jj = 0; jj < 2; ++jj) {
                    asm volatile(
                        "mma.sync.aligned.m16n8k16.row.col.f32.f16.f16.f32 "
                        "{%0,%1,%2,%3}, {%4,%5,%6,%7}, {%8,%9}, {%0,%1,%2,%3};"
                        : "+f"(acc[f][2 * jj][0]), "+f"(acc[f][2 * jj][1]),
                          "+f"(acc[f][2 * jj][2]), "+f"(acc[f][2 * jj][3])
                        : "r"(a[f][0]), "r"(a[f][1]), "r"(a[f][2]), "r"(a[f][3]),
                          "r"(bq[jj][0]), "r"(bq[jj][1]));
                    asm volatile(
                        "mma.sync.aligned.m16n8k16.row.col.f32.f16.f16.f32 "
                        "{%0,%1,%2,%3}, {%4,%5,%6,%7}, {%8,%9}, {%0,%1,%2,%3};"
                        : "+f"(acc[f][2 * jj + 1][0]), "+f"(acc[f][2 * jj + 1][1]),
                          "+f"(acc[f][2 * jj + 1][2]), "+f"(acc[f][2 * jj + 1][3])
                        : "r"(a[f][0]), "r"(a[f][1]), "r"(a[f][2]), "r"(a[f][3]),
                          "r"(bq[jj][2]), "r"(bq[jj][3]));
                }
        }
    }

    // epilogue: warp covers 64 m x 32 n of the 128x128 tile
#pragma unroll
    for (int f = 0; f < 4; ++f) {
        int co = mb + 16 * f + qid;
        float* o0 = out + ((size_t)(b * CO + co)) * HW + (nt << 7) + nb + 2 * tig;
        float* o1 = o0 + 8 * HW;
#pragma unroll
        for (int j = 0; j < 4; ++j) {
            *(float2*)(o0 + 8 * j) = make_float2(acc[f][j][0], acc[f][j][1]);
            *(float2*)(o1 + 8 * j) = make_float2(acc[f][j][2], acc[f][j][3]);
        }
    }
}

extern "C" void kernel_launch(void* const* d_in, const int* in_sizes, int n_in,
                              void* d_out, int out_size) {
    const float* feat = (const float*)d_in[0];   // (16,128,64,64)
    const float* wker = (const float*)d_in[1];   // (16,128,128,3,3)
    float* out = (float*)d_out;

    cudaFuncSetAttribute(conv_kernel, cudaFuncAttributeMaxDynamicSharedMemorySize, SMEM_BYTES);

    prep_fused<<<1280, 256>>>(feat, wker);
    conv_kernel<<<dim3(32, BB), 256, SMEM_BYTES>>>(out);
}